// round 16
// baseline (speedup 1.0000x reference)
#include <cuda_runtime.h>
#include <cuda_fp16.h>
#include <math.h>
#include <stdint.h>

#define D_MODEL 1024
#define NH 16
#define HD 64
#define BSZ 2
#define SEQL 2048
#define MTOT (BSZ*SEQL)

// scratch (allocation-free) — fp16 pipeline
__device__ __half g_x16[(size_t)MTOT*D_MODEL];
__device__ __half g_w16[4][(size_t)D_MODEL*D_MODEL];
__device__ __half g_q16[(size_t)BSZ*NH*SEQL*HD];
__device__ __half g_k16[(size_t)BSZ*NH*SEQL*HD];
__device__ __half g_vt[(size_t)BSZ*NH*HD*SEQL];      // V transposed [bh][d][s]
__device__ __half g_attn16[(size_t)MTOT*D_MODEL];
__device__ float2 g_rope[(size_t)SEQL*(HD/2)];       // (cos,sin) per (s, pair)

// log2(e)/8 : folded into Q so softmax uses exp2
#define QSCALE 0.18033688011112042f

__device__ __forceinline__ uint32_t pf16x2(float lo, float hi) {
    uint32_t r;
    asm("cvt.rn.f16x2.f32 %0, %1, %2;" : "=r"(r) : "f"(hi), "f"(lo));
    return r;
}

__device__ __forceinline__ float ex2(float x) {
    float y;
    asm("ex2.approx.ftz.f32 %0, %1;" : "=f"(y) : "f"(x));
    return y;
}

__device__ __forceinline__ uint32_t ex2h2(uint32_t a) {
    uint32_t r;
    asm("ex2.approx.f16x2 %0, %1;" : "=r"(r) : "r"(a));
    return r;
}

__device__ __forceinline__ uint32_t hadd2u(uint32_t a, uint32_t b) {
    uint32_t r;
    asm("add.rn.f16x2 %0, %1, %2;" : "=r"(r) : "r"(a), "r"(b));
    return r;
}

__device__ __forceinline__ void mma_f16(float* c, uint32_t a0, uint32_t a1,
                                        uint32_t a2, uint32_t a3,
                                        uint32_t b0, uint32_t b1) {
    asm volatile(
        "mma.sync.aligned.m16n8k16.row.col.f32.f16.f16.f32 "
        "{%0,%1,%2,%3}, {%4,%5,%6,%7}, {%8,%9}, {%0,%1,%2,%3};"
        : "+f"(c[0]), "+f"(c[1]), "+f"(c[2]), "+f"(c[3])
        : "r"(a0), "r"(a1), "r"(a2), "r"(a3), "r"(b0), "r"(b1));
}

__device__ __forceinline__ void ldm4(uint32_t* r, uint32_t addr) {
    asm volatile("ldmatrix.sync.aligned.m8n8.x4.shared.b16 {%0,%1,%2,%3}, [%4];"
                 : "=r"(r[0]), "=r"(r[1]), "=r"(r[2]), "=r"(r[3]) : "r"(addr));
}

__device__ __forceinline__ void cpa16(uint32_t dst, const void* src) {
    asm volatile("cp.async.cg.shared.global [%0], [%1], 16;" :: "r"(dst), "l"(src));
}
__device__ __forceinline__ void cpa_commit() { asm volatile("cp.async.commit_group;"); }
__device__ __forceinline__ void cpa_wait2()  { asm volatile("cp.async.wait_group 2;"); }
__device__ __forceinline__ void cpa_wait1()  { asm volatile("cp.async.wait_group 1;"); }
__device__ __forceinline__ void cpa_wait0()  { asm volatile("cp.async.wait_group 0;"); }

// ---------------------------------------------------------------------------
// one-time converts + RoPE table, single launch
// ---------------------------------------------------------------------------
#define NCVT (MTOT * D_MODEL / 8 + 4 * (D_MODEL * D_MODEL / 8))   // 1048576

__global__ void cvt_all(const float4* __restrict__ x,
                        const float4* __restrict__ w0, const float4* __restrict__ w1,
                        const float4* __restrict__ w2, const float4* __restrict__ w3,
                        const int* __restrict__ tokpos)
{
    int i = blockIdx.x * blockDim.x + threadIdx.x;
    if (i < NCVT) {
        const float4* src;
        uint4* dst;
        int j;
        if (i < (MTOT * D_MODEL / 8)) {
            src = x; dst = (uint4*)g_x16; j = i;
        } else {
            int r = i - (MTOT * D_MODEL / 8);
            int w = r >> 17;
            j = r & 131071;
            src = w == 0 ? w0 : w == 1 ? w1 : w == 2 ? w2 : w3;
            dst = (uint4*)g_w16[w];
        }
        float4 a = src[2 * j], b = src[2 * j + 1];
        uint4 o;
        o.x = pf16x2(a.x, a.y); o.y = pf16x2(a.z, a.w);
        o.z = pf16x2(b.x, b.y); o.w = pf16x2(b.z, b.w);
        dst[j] = o;
    } else {
        int r = i - NCVT;                 // 0..65535
        int s = r >> 5, j = r & 31;
        float pos = (float)tokpos[s];
        float fr = ex2((float)(2 * j) * (-13.287712379549449f / 64.f));
        float cs, sn;
        sincosf(pos * fr, &sn, &cs);
        g_rope[r] = make_float2(cs, sn);
    }
}

// ---------------------------------------------------------------------------
// fp16 GEMM (byte-exact R13/R10): CTA 128x128, BK=32, 4 warps, 64x64 warp
// tile, ldmatrix.x4, 3-stage cp.async.
// mode 0: fp32 out; 1: RoPE*QSCALE->fp16 Q; 3: RoPE->fp16 K; 2: fp16 V^T
// ---------------------------------------------------------------------------
#define GSTR 40
#define GST (128*GSTR)
#define GEMM_SMEM (3*2*GST*2)

__global__ __launch_bounds__(128)
void gemm_f16(const __half* __restrict__ A,
              const __half* __restrict__ W0, const __half* __restrict__ W1,
              const __half* __restrict__ W2,
              float* __restrict__ o0,
              __half* __restrict__ h0, __half* __restrict__ h1,
              __half* __restrict__ vt,
              int md0, int md1, int md2)
{
    extern __shared__ __half smh[];
    const int z = blockIdx.z;
    const __half* W = z == 0 ? W0 : z == 1 ? W1 : W2;
    const int mode = z == 0 ? md0 : z == 1 ? md1 : md2;
    __half* outh    = z == 0 ? h0 : h1;

    const int tid = (int)threadIdx.x;
    const int m0 = blockIdx.y * 128, n0 = blockIdx.x * 128;
    const int lane = tid & 31, wid = tid >> 5;
    const int g = lane >> 2, t = lane & 3;
    const int wm = (wid >> 1) * 64, wn = (wid & 1) * 64;

    uint32_t sbase = (uint32_t)__cvta_generic_to_shared(smh);

    const int aoff = (wm + (lane & 15)) * GSTR + (lane >> 4) * 8;
    const int boff = (wn + (lane >> 4) * 8 + (lane & 7)) * GSTR + ((lane >> 3) & 1) * 8;

    float c[4][8][4];
#pragma unroll
    for (int i = 0; i < 4; ++i)
#pragma unroll
        for (int j = 0; j < 8; ++j)
#pragma unroll
            for (int k = 0; k < 4; ++k) c[i][j][k] = 0.f;

#define ISSUE(stage, k0)                                                         \
    {                                                                            \
        uint32_t as_ = sbase + (uint32_t)(stage) * (2 * GST * 2);                \
        uint32_t bs_ = as_ + GST * 2;                                            \
        _Pragma("unroll")                                                        \
        for (int i_ = 0; i_ < 4; ++i_) {                                         \
            int lin_ = tid + i_ * 128;                                           \
            int row_ = lin_ >> 2;                                                \
            int cc_ = (lin_ & 3) * 8;                                            \
            cpa16(as_ + (uint32_t)(row_ * GSTR + cc_) * 2,                       \
                  A + (size_t)(m0 + row_) * D_MODEL + (k0) + cc_);               \
            cpa16(bs_ + (uint32_t)(row_ * GSTR + cc_) * 2,                       \
                  W + (size_t)(n0 + row_) * D_MODEL + (k0) + cc_);               \
        }                                                                        \
        cpa_commit();                                                            \
    }

    ISSUE(0, 0);
    ISSUE(1, 32);
    ISSUE(2, 64);

    int stage = 0;
    for (int kt = 0; kt < 32; ++kt) {
        cpa_wait2();
        __syncthreads();
        uint32_t abase = sbase + (uint32_t)stage * (2 * GST * 2) + (uint32_t)aoff * 2;
        uint32_t bbase = sbase + (uint32_t)stage * (2 * GST * 2) + GST * 2
                       + (uint32_t)boff * 2;

#pragma unroll
        for (int ks = 0; ks < 2; ++ks) {
            uint32_t af[4][4], bf[4][4];
#pragma unroll
            for (int mt = 0; mt < 4; ++mt)
                ldm4(af[mt], abase + (uint32_t)(mt * 16 * GSTR + ks * 16) * 2);
#pragma unroll
            for (int np = 0; np < 4; ++np)
                ldm4(bf[np], bbase + (uint32_t)(np * 16 * GSTR + ks * 16) * 2);
#pragma unroll
            for (int mt = 0; mt < 4; ++mt)
#pragma unroll
                for (int np = 0; np < 4; ++np) {
                    mma_f16(c[mt][2 * np],     af[mt][0], af[mt][1], af[mt][2],
                            af[mt][3], bf[np][0], bf[np][1]);
                    mma_f16(c[mt][2 * np + 1], af[mt][0], af[mt][1], af[mt][2],
                            af[mt][3], bf[np][2], bf[np][3]);
                }
        }
        __syncthreads();
        if (kt + 3 < 32) { ISSUE(stage, (kt + 3) * 32); }
        else             { cpa_commit(); }
        stage = stage == 2 ? 0 : stage + 1;
    }

    if (mode == 0) {
#pragma unroll
        for (int mt = 0; mt < 4; ++mt) {
            int rowa = m0 + wm + mt * 16 + g;
#pragma unroll
            for (int j = 0; j < 8; ++j) {
                int col = n0 + wn + j * 8 + 2 * t;
                *(float2*)(o0 + (size_t)rowa * D_MODEL + col) =
                    make_float2(c[mt][j][0], c[mt][j][1]);
                *(float2*)(o0 + (size_t)(rowa + 8) * D_MODEL + col) =
                    make_float2(c[mt][j][2], c[mt][j][3]);
            }
        }
    } else {
#pragma unroll
        for (int mt = 0; mt < 4; ++mt) {
#pragma unroll
            for (int half = 0; half < 2; ++half) {
                int m = m0 + wm + mt * 16 + g + half * 8;
                int b = m >> 11;
                int s = m & (SEQL - 1);
#pragma unroll
                for (int j = 0; j < 8; ++j) {
                    int col = n0 + wn + j * 8 + 2 * t;   // even
                    int h = col >> 6;
                    int d = col & 63;
                    float e = c[mt][j][half * 2 + 0];
                    float o = c[mt][j][half * 2 + 1];
                    if (mode != 2) {
                        float2 r = g_rope[s * 32 + (d >> 1)];
                        float re = e * r.x - o * r.y;
                        float ro = e * r.y + o * r.x;
                        if (mode == 1) { re *= QSCALE; ro *= QSCALE; }
                        size_t dst = ((size_t)(b * NH + h) * SEQL + s) * HD + d;
                        *(uint32_t*)(outh + dst) = pf16x2(re, ro);
                    } else {
                        size_t dst = ((size_t)(b * NH + h) * HD + d) * SEQL + s;
                        vt[dst]        = __float2half(e);
                        vt[dst + SEQL] = __float2half(o);
                    }
                }
            }
        }
    }
}

// ---------------------------------------------------------------------------
// Flash attention. 128 threads (4 warps), QT=64, KT=64, 2-buffer cp.async.
// K/V B-operands via ldmatrix.x4. NEW: softmax exp via ex2.approx.f16x2
// (half the MUFU ops; result doubles as the PV A-fragment), row-sum in f16x2.
// ---------------------------------------------------------------------------
#define FSTR 72
#define KBYTES (64 * FSTR * 2)
#define VBYTES (64 * FSTR * 2)
#define FLASH_SMEM (2 * KBYTES + 2 * VBYTES)

__device__ __forceinline__ void kv_issue(uint32_t sbase, int stage,
                                         const __half* Kp,
                                         const __half* Vtp,
                                         int tile, int tid)
{
    uint32_t dK = sbase + (uint32_t)stage * KBYTES;
    uint32_t dV = sbase + 2 * KBYTES + (uint32_t)stage * VBYTES;
#pragma unroll
    for (int i = 0; i < 4; ++i) {
        int lin = tid + i * 128;
        int row = lin >> 3;
        int cc = (lin & 7) * 8;
        cpa16(dK + (uint32_t)(row * FSTR + cc) * 2,
              Kp + (size_t)(tile * 64 + row) * HD + cc);
        cpa16(dV + (uint32_t)(row * FSTR + cc) * 2,
              Vtp + (size_t)row * SEQL + tile * 64 + cc);
    }
    cpa_commit();
}

__global__ __launch_bounds__(128)
void flash_mma(__half* __restrict__ attnout)
{
    extern __shared__ __half smh[];
    uint32_t sbase = (uint32_t)__cvta_generic_to_shared(smh);

    const int qt = (int)(gridDim.x - 1 - blockIdx.x);
    const int bh = (int)blockIdx.y;
    const int b  = bh >> 4;
    const int h  = bh & 15;
    const int tid = (int)threadIdx.x;
    const int wid = tid >> 5, lane = tid & 31;
    const int g = lane >> 2, t = lane & 3;
    const int wm = wid * 16;

    const int lm = lane >> 3, lr = lane & 7;
    const uint32_t ldoff = (uint32_t)(((8 * (lm >> 1) + lr) * FSTR + (lm & 1) * 8) * 2);

    const __half* Qp = g_q16 + (size_t)bh * SEQL * HD;
    const __half* Kp = g_k16 + (size_t)bh * SEQL * HD;
    const __half* Vtp = g_vt + (size_t)bh * HD * SEQL;

#pragma unroll
    for (int i = 0; i < 4; ++i) {
        int lin = tid + i * 128;
        int row = lin >> 3;
        int cc = (lin & 7) * 8;
        *(uint4*)&smh[row * FSTR + cc] =
            *(const uint4*)(Qp + (size_t)(qt * 64 + row) * HD + cc);
    }
    __syncthreads();
    uint32_t aq[4][4];
#pragma unroll
    for (int ks = 0; ks < 4; ++ks) {
        const __half* p = smh + (wm + g) * FSTR + ks * 16 + 2 * t;
        aq[ks][0] = *(const uint32_t*)p;
        aq[ks][1] = *(const uint32_t*)(p + 8 * FSTR);
        aq[ks][2] = *(const uint32_t*)(p + 8);
        aq[ks][3] = *(const uint32_t*)(p + 8 * FSTR + 8);
    }
    __syncthreads();

    float m0 = -1e30f, m1 = -1e30f, l0 = 0.f, l1 = 0.f;
    float o[8][4];
#pragma unroll
    for (int n = 0; n < 8; ++n)
#pragma unroll
        for (int e = 0; e < 4; ++e) o[n][e] = 0.f;

    kv_issue(sbase, 0, Kp, Vtp, 0, tid);
    if (qt > 0) kv_issue(sbase, 1, Kp, Vtp, 1, tid);

    for (int kt = 0; kt <= qt; ++kt) {
        const int cur = kt & 1;
        if (kt < qt) cpa_wait1(); else cpa_wait0();
        __syncthreads();
        const uint32_t K0u = sbase + (uint32_t)cur * KBYTES + ldoff;
        const uint32_t Vtu = sbase + 2 * KBYTES + (uint32_t)cur * VBYTES + ldoff;

        // S = Q @ K^T
        float cs[8][4];
#pragma unroll
        for (int n = 0; n < 8; ++n)
#pragma unroll
            for (int e = 0; e < 4; ++e) cs[n][e] = 0.f;
#pragma unroll
        for (int ks = 0; ks < 4; ++ks) {
#pragma unroll
            for (int j = 0; j < 4; ++j) {
                uint32_t bf[4];
                ldm4(bf, K0u + (uint32_t)((16 * j) * FSTR + 16 * ks) * 2);
                mma_f16(cs[2 * j],     aq[ks][0], aq[ks][1], aq[ks][2], aq[ks][3],
                        bf[0], bf[1]);
                mma_f16(cs[2 * j + 1], aq[ks][0], aq[ks][1], aq[ks][2], aq[ks][3],
                        bf[2], bf[3]);
            }
        }

        if (kt == qt) {
            const int rowg = wm + g;
#pragma unroll
            for (int n = 0; n < 8; ++n) {
                int col = n * 8 + 2 * t;
                if (col     > rowg)     cs[n][0] = -1e30f;
                if (col + 1 > rowg)     cs[n][1] = -1e30f;
                if (col     > rowg + 8) cs[n][2] = -1e30f;
                if (col + 1 > rowg + 8) cs[n][3] = -1e30f;
            }
        }

        float mx0 = -1e30f, mx1 = -1e30f;
#pragma unroll
        for (int n = 0; n < 8; ++n) {
            mx0 = fmaxf(mx0, fmaxf(cs[n][0], cs[n][1]));
            mx1 = fmaxf(mx1, fmaxf(cs[n][2], cs[n][3]));
        }
        mx0 = fmaxf(mx0, __shfl_xor_sync(0xffffffffu, mx0, 1));
        mx0 = fmaxf(mx0, __shfl_xor_sync(0xffffffffu, mx0, 2));
        mx1 = fmaxf(mx1, __shfl_xor_sync(0xffffffffu, mx1, 1));
        mx1 = fmaxf(mx1, __shfl_xor_sync(0xffffffffu, mx1, 2));
        float mn0 = fmaxf(m0, mx0), mn1 = fmaxf(m1, mx1);
        float a0 = ex2(m0 - mn0), a1 = ex2(m1 - mn1);

        // probs via f16x2 exp2: pa = exp2(cs - mn) packed; sums in f16x2
        uint32_t pa0[8], pa1[8];
        uint32_t hs0 = 0u, hs1 = 0u;     // f16x2 zero
#pragma unroll
        for (int n = 0; n < 8; ++n) {
            pa0[n] = ex2h2(pf16x2(cs[n][0] - mn0, cs[n][1] - mn0));
            pa1[n] = ex2h2(pf16x2(cs[n][2] - mn1, cs[n][3] - mn1));
            hs0 = hadd2u(hs0, pa0[n]);
            hs1 = hadd2u(hs1, pa1[n]);
        }
        __half2 h0v = *(__half2*)&hs0;
        __half2 h1v = *(__half2*)&hs1;
        float s0 = __half2float(h0v.x) + __half2float(h0v.y);
        float s1 = __half2float(h1v.x) + __half2float(h1v.y);
        s0 += __shfl_xor_sync(0xffffffffu, s0, 1);
        s0 += __shfl_xor_sync(0xffffffffu, s0, 2);
        s1 += __shfl_xor_sync(0xffffffffu, s1, 1);
        s1 += __shfl_xor_sync(0xffffffffu, s1, 2);
        l0 = l0 * a0 + s0;
        l1 = l1 * a1 + s1;
        m0 = mn0; m1 = mn1;
#pragma unroll
        for (int n = 0; n < 8; ++n) {
            o[n][0] *= a0; o[n][1] *= a0;
            o[n][2] *= a1; o[n][3] *= a1;
        }

        // O += P @ V
#pragma unroll
        for (int ks = 0; ks < 4; ++ks) {
            uint32_t a0r = pa0[2 * ks],     a1r = pa1[2 * ks];
            uint32_t a2r = pa0[2 * ks + 1], a3r = pa1[2 * ks + 1];
#pragma unroll
            for (int j = 0; j < 4; ++j) {
                uint32_t vf[4];
                ldm4(vf, Vtu + (uint32_t)((16 * j) * FSTR + 16 * ks) * 2);
                mma_f16(o[2 * j],     a0r, a1r, a2r, a3r, vf[0], vf[1]);
                mma_f16(o[2 * j + 1], a0r, a1r, a2r, a3r, vf[2], vf[3]);
            }
        }
        __syncthreads();
        if (kt + 2 <= qt) kv_issue(sbase, cur, Kp, Vtp, kt + 2, tid);
    }

    float i0 = 1.f / l0, i1 = 1.f / l1;
    __half* d0 = attnout + ((size_t)(b * SEQL) + qt * 64 + wm + g) * D_MODEL + h * HD;
#pragma unroll
    for (int n = 0; n < 8; ++n) {
        int col = n * 8 + 2 * t;
        *(uint32_t*)(d0 + col) = pf16x2(o[n][0] * i0, o[n][1] * i0);
        *(uint32_t*)(d0 + 8 * D_MODEL + col) = pf16x2(o[n][2] * i1, o[n][3] * i1);
    }
}

// ---------------------------------------------------------------------------
extern "C" void kernel_launch(void* const* d_in, const int* in_sizes, int n_in,
                              void* d_out, int out_size)
{
    const float* x  = (const float*)d_in[0];
    const int*   tp = (const int*)d_in[1];
    const float* Wq = (const float*)d_in[2];
    const float* Wk = (const float*)d_in[3];
    const float* Wv = (const float*)d_in[4];
    const float* Wo = (const float*)d_in[5];
    float* out = (float*)d_out;

    __half *x16p, *w16p, *q16p, *k16p, *vtp, *a16p;
    cudaGetSymbolAddress((void**)&x16p, g_x16);
    cudaGetSymbolAddress((void**)&w16p, g_w16);
    cudaGetSymbolAddress((void**)&q16p, g_q16);
    cudaGetSymbolAddress((void**)&k16p, g_k16);
    cudaGetSymbolAddress((void**)&vtp, g_vt);
    cudaGetSymbolAddress((void**)&a16p, g_attn16);

    static int inited = 0;
    if (!inited) {
        cudaFuncSetAttribute(gemm_f16, cudaFuncAttributeMaxDynamicSharedMemorySize,
                             GEMM_SMEM);
        cudaFuncSetAttribute(flash_mma, cudaFuncAttributeMaxDynamicSharedMemorySize,
                             FLASH_SMEM);
        inited = 1;
    }

    const __half* w0 = w16p;
    const __half* w1 = w16p + (size_t)D_MODEL * D_MODEL;
    const __half* w2 = w16p + 2 * (size_t)D_MODEL * D_MODEL;
    const __half* w3 = w16p + 3 * (size_t)D_MODEL * D_MODEL;

    // converts + RoPE table in one launch
    cvt_all<<<(NCVT + SEQL * 32) / 256, 256>>>(
        (const float4*)x, (const float4*)Wq, (const float4*)Wk,
        (const float4*)Wv, (const float4*)Wo, tp);

    // fused QKV projection (+RoPE table, Q scale; fp16 outputs; V transposed)
    gemm_f16<<<dim3(D_MODEL / 128, MTOT / 128, 3), 128, GEMM_SMEM>>>(
        x16p, w0, w1, w2, out, q16p, k16p, vtp, 1, 3, 2);

    flash_mma<<<dim3(SEQL / 64, BSZ * NH), 128, FLASH_SMEM>>>(a16p);

    // output projection (fp32 result)
    gemm_f16<<<dim3(D_MODEL / 128, MTOT / 128, 1), 128, GEMM_SMEM>>>(
        a16p, w3, w3, w3, out, q16p, k16p, vtp, 0, 0, 0);
}

// round 17
// speedup vs baseline: 1.0162x; 1.0162x over previous
#include <cuda_runtime.h>
#include <cuda_fp16.h>
#include <math.h>
#include <stdint.h>

#define D_MODEL 1024
#define NH 16
#define HD 64
#define BSZ 2
#define SEQL 2048
#define MTOT (BSZ*SEQL)

// scratch (allocation-free) — fp16 pipeline
__device__ __half g_x16[(size_t)MTOT*D_MODEL];
__device__ __half g_w16[4][(size_t)D_MODEL*D_MODEL];
__device__ __half g_q16[(size_t)BSZ*NH*SEQL*HD];
__device__ __half g_k16[(size_t)BSZ*NH*SEQL*HD];
__device__ __half g_vt[(size_t)BSZ*NH*HD*SEQL];      // V transposed [bh][d][s]
__device__ __half g_attn16[(size_t)MTOT*D_MODEL];
__device__ float2 g_rope[(size_t)SEQL*(HD/2)];       // (cos,sin) per (s, pair)

// log2(e)/8 : folded into Q so softmax uses exp2
#define QSCALE 0.18033688011112042f

__device__ __forceinline__ uint32_t pf16x2(float lo, float hi) {
    uint32_t r;
    asm("cvt.rn.f16x2.f32 %0, %1, %2;" : "=r"(r) : "f"(hi), "f"(lo));
    return r;
}

__device__ __forceinline__ float ex2(float x) {
    float y;
    asm("ex2.approx.ftz.f32 %0, %1;" : "=f"(y) : "f"(x));
    return y;
}

__device__ __forceinline__ void mma_f16(float* c, uint32_t a0, uint32_t a1,
                                        uint32_t a2, uint32_t a3,
                                        uint32_t b0, uint32_t b1) {
    asm volatile(
        "mma.sync.aligned.m16n8k16.row.col.f32.f16.f16.f32 "
        "{%0,%1,%2,%3}, {%4,%5,%6,%7}, {%8,%9}, {%0,%1,%2,%3};"
        : "+f"(c[0]), "+f"(c[1]), "+f"(c[2]), "+f"(c[3])
        : "r"(a0), "r"(a1), "r"(a2), "r"(a3), "r"(b0), "r"(b1));
}

__device__ __forceinline__ void ldm4(uint32_t* r, uint32_t addr) {
    asm volatile("ldmatrix.sync.aligned.m8n8.x4.shared.b16 {%0,%1,%2,%3}, [%4];"
                 : "=r"(r[0]), "=r"(r[1]), "=r"(r[2]), "=r"(r[3]) : "r"(addr));
}

__device__ __forceinline__ void cpa16(uint32_t dst, const void* src) {
    asm volatile("cp.async.cg.shared.global [%0], [%1], 16;" :: "r"(dst), "l"(src));
}
__device__ __forceinline__ void cpa_commit() { asm volatile("cp.async.commit_group;"); }
__device__ __forceinline__ void cpa_wait1()  { asm volatile("cp.async.wait_group 1;"); }
__device__ __forceinline__ void cpa_wait0()  { asm volatile("cp.async.wait_group 0;"); }

// ---------------------------------------------------------------------------
// one-time converts + RoPE table, single launch
// ---------------------------------------------------------------------------
#define NCVT (MTOT * D_MODEL / 8 + 4 * (D_MODEL * D_MODEL / 8))   // 1048576

__global__ void cvt_all(const float4* __restrict__ x,
                        const float4* __restrict__ w0, const float4* __restrict__ w1,
                        const float4* __restrict__ w2, const float4* __restrict__ w3,
                        const int* __restrict__ tokpos)
{
    int i = blockIdx.x * blockDim.x + threadIdx.x;
    if (i < NCVT) {
        const float4* src;
        uint4* dst;
        int j;
        if (i < (MTOT * D_MODEL / 8)) {
            src = x; dst = (uint4*)g_x16; j = i;
        } else {
            int r = i - (MTOT * D_MODEL / 8);
            int w = r >> 17;
            j = r & 131071;
            src = w == 0 ? w0 : w == 1 ? w1 : w == 2 ? w2 : w3;
            dst = (uint4*)g_w16[w];
        }
        float4 a = src[2 * j], b = src[2 * j + 1];
        uint4 o;
        o.x = pf16x2(a.x, a.y); o.y = pf16x2(a.z, a.w);
        o.z = pf16x2(b.x, b.y); o.w = pf16x2(b.z, b.w);
        dst[j] = o;
    } else {
        int r = i - NCVT;                 // 0..65535
        int s = r >> 5, j = r & 31;
        float pos = (float)tokpos[s];
        float fr = ex2((float)(2 * j) * (-13.287712379549449f / 64.f));
        float cs, sn;
        sincosf(pos * fr, &sn, &cs);
        g_rope[r] = make_float2(cs, sn);
    }
}

// ---------------------------------------------------------------------------
// fp16 GEMM: CTA 128x128, BK=32, 4 warps, 64x64 warp tile, ldmatrix.x4,
// 2-stage cp.async (41KB smem -> 5 CTAs/SM resident, QKV fits ~1 wave).
// mode 0: fp32 out; 1: RoPE*QSCALE->fp16 Q; 3: RoPE->fp16 K; 2: fp16 V^T
// ---------------------------------------------------------------------------
#define GSTR 40
#define GST (128*GSTR)
#define GEMM_SMEM (2*2*GST*2)            // 40960 B

__global__ __launch_bounds__(128)
void gemm_f16(const __half* __restrict__ A,
              const __half* __restrict__ W0, const __half* __restrict__ W1,
              const __half* __restrict__ W2,
              float* __restrict__ o0,
              __half* __restrict__ h0, __half* __restrict__ h1,
              __half* __restrict__ vt,
              int md0, int md1, int md2)
{
    extern __shared__ __half smh[];
    const int z = blockIdx.z;
    const __half* W = z == 0 ? W0 : z == 1 ? W1 : W2;
    const int mode = z == 0 ? md0 : z == 1 ? md1 : md2;
    __half* outh    = z == 0 ? h0 : h1;

    const int tid = (int)threadIdx.x;
    const int m0 = blockIdx.y * 128, n0 = blockIdx.x * 128;
    const int lane = tid & 31, wid = tid >> 5;
    const int g = lane >> 2, t = lane & 3;
    const int wm = (wid >> 1) * 64, wn = (wid & 1) * 64;

    uint32_t sbase = (uint32_t)__cvta_generic_to_shared(smh);

    const int aoff = (wm + (lane & 15)) * GSTR + (lane >> 4) * 8;
    const int boff = (wn + (lane >> 4) * 8 + (lane & 7)) * GSTR + ((lane >> 3) & 1) * 8;

    float c[4][8][4];
#pragma unroll
    for (int i = 0; i < 4; ++i)
#pragma unroll
        for (int j = 0; j < 8; ++j)
#pragma unroll
            for (int k = 0; k < 4; ++k) c[i][j][k] = 0.f;

#define ISSUE(stage, k0)                                                         \
    {                                                                            \
        uint32_t as_ = sbase + (uint32_t)(stage) * (2 * GST * 2);                \
        uint32_t bs_ = as_ + GST * 2;                                            \
        _Pragma("unroll")                                                        \
        for (int i_ = 0; i_ < 4; ++i_) {                                         \
            int lin_ = tid + i_ * 128;                                           \
            int row_ = lin_ >> 2;                                                \
            int cc_ = (lin_ & 3) * 8;                                            \
            cpa16(as_ + (uint32_t)(row_ * GSTR + cc_) * 2,                       \
                  A + (size_t)(m0 + row_) * D_MODEL + (k0) + cc_);               \
            cpa16(bs_ + (uint32_t)(row_ * GSTR + cc_) * 2,                       \
                  W + (size_t)(n0 + row_) * D_MODEL + (k0) + cc_);               \
        }                                                                        \
        cpa_commit();                                                            \
    }

    ISSUE(0, 0);
    ISSUE(1, 32);

    for (int kt = 0; kt < 32; ++kt) {
        const int stage = kt & 1;
        cpa_wait1();
        __syncthreads();
        uint32_t abase = sbase + (uint32_t)stage * (2 * GST * 2) + (uint32_t)aoff * 2;
        uint32_t bbase = sbase + (uint32_t)stage * (2 * GST * 2) + GST * 2
                       + (uint32_t)boff * 2;

#pragma unroll
        for (int ks = 0; ks < 2; ++ks) {
            uint32_t af[4][4], bf[4][4];
#pragma unroll
            for (int mt = 0; mt < 4; ++mt)
                ldm4(af[mt], abase + (uint32_t)(mt * 16 * GSTR + ks * 16) * 2);
#pragma unroll
            for (int np = 0; np < 4; ++np)
                ldm4(bf[np], bbase + (uint32_t)(np * 16 * GSTR + ks * 16) * 2);
#pragma unroll
            for (int mt = 0; mt < 4; ++mt)
#pragma unroll
                for (int np = 0; np < 4; ++np) {
                    mma_f16(c[mt][2 * np],     af[mt][0], af[mt][1], af[mt][2],
                            af[mt][3], bf[np][0], bf[np][1]);
                    mma_f16(c[mt][2 * np + 1], af[mt][0], af[mt][1], af[mt][2],
                            af[mt][3], bf[np][2], bf[np][3]);
                }
        }
        __syncthreads();
        if (kt + 2 < 32) { ISSUE(stage, (kt + 2) * 32); }
        else             { cpa_commit(); }
    }

    if (mode == 0) {
#pragma unroll
        for (int mt = 0; mt < 4; ++mt) {
            int rowa = m0 + wm + mt * 16 + g;
#pragma unroll
            for (int j = 0; j < 8; ++j) {
                int col = n0 + wn + j * 8 + 2 * t;
                *(float2*)(o0 + (size_t)rowa * D_MODEL + col) =
                    make_float2(c[mt][j][0], c[mt][j][1]);
                *(float2*)(o0 + (size_t)(rowa + 8) * D_MODEL + col) =
                    make_float2(c[mt][j][2], c[mt][j][3]);
            }
        }
    } else {
#pragma unroll
        for (int mt = 0; mt < 4; ++mt) {
#pragma unroll
            for (int half = 0; half < 2; ++half) {
                int m = m0 + wm + mt * 16 + g + half * 8;
                int b = m >> 11;
                int s = m & (SEQL - 1);
#pragma unroll
                for (int j = 0; j < 8; ++j) {
                    int col = n0 + wn + j * 8 + 2 * t;   // even
                    int h = col >> 6;
                    int d = col & 63;
                    float e = c[mt][j][half * 2 + 0];
                    float o = c[mt][j][half * 2 + 1];
                    if (mode != 2) {
                        float2 r = g_rope[s * 32 + (d >> 1)];
                        float re = e * r.x - o * r.y;
                        float ro = e * r.y + o * r.x;
                        if (mode == 1) { re *= QSCALE; ro *= QSCALE; }
                        size_t dst = ((size_t)(b * NH + h) * SEQL + s) * HD + d;
                        *(uint32_t*)(outh + dst) = pf16x2(re, ro);
                    } else {
                        size_t dst = ((size_t)(b * NH + h) * HD + d) * SEQL + s;
                        vt[dst]        = __float2half(e);
                        vt[dst + SEQL] = __float2half(o);
                    }
                }
            }
        }
    }
}

// ---------------------------------------------------------------------------
// Flash attention (byte-exact R15, best measured). 128 threads, QT=64, KT=64,
// 2-buffer cp.async, K/V B-operands via ldmatrix.x4, P from registers,
// fp32 ex2 softmax.
// ---------------------------------------------------------------------------
#define FSTR 72
#define KBYTES (64 * FSTR * 2)
#define VBYTES (64 * FSTR * 2)
#define FLASH_SMEM (2 * KBYTES + 2 * VBYTES)

__device__ __forceinline__ void kv_issue(uint32_t sbase, int stage,
                                         const __half* Kp,
                                         const __half* Vtp,
                                         int tile, int tid)
{
    uint32_t dK = sbase + (uint32_t)stage * KBYTES;
    uint32_t dV = sbase + 2 * KBYTES + (uint32_t)stage * VBYTES;
#pragma unroll
    for (int i = 0; i < 4; ++i) {
        int lin = tid + i * 128;
        int row = lin >> 3;
        int cc = (lin & 7) * 8;
        cpa16(dK + (uint32_t)(row * FSTR + cc) * 2,
              Kp + (size_t)(tile * 64 + row) * HD + cc);
        cpa16(dV + (uint32_t)(row * FSTR + cc) * 2,
              Vtp + (size_t)row * SEQL + tile * 64 + cc);
    }
    cpa_commit();
}

__global__ __launch_bounds__(128)
void flash_mma(__half* __restrict__ attnout)
{
    extern __shared__ __half smh[];
    uint32_t sbase = (uint32_t)__cvta_generic_to_shared(smh);

    const int qt = (int)(gridDim.x - 1 - blockIdx.x);
    const int bh = (int)blockIdx.y;
    const int b  = bh >> 4;
    const int h  = bh & 15;
    const int tid = (int)threadIdx.x;
    const int wid = tid >> 5, lane = tid & 31;
    const int g = lane >> 2, t = lane & 3;
    const int wm = wid * 16;

    const int lm = lane >> 3, lr = lane & 7;
    const uint32_t ldoff = (uint32_t)(((8 * (lm >> 1) + lr) * FSTR + (lm & 1) * 8) * 2);

    const __half* Qp = g_q16 + (size_t)bh * SEQL * HD;
    const __half* Kp = g_k16 + (size_t)bh * SEQL * HD;
    const __half* Vtp = g_vt + (size_t)bh * HD * SEQL;

#pragma unroll
    for (int i = 0; i < 4; ++i) {
        int lin = tid + i * 128;
        int row = lin >> 3;
        int cc = (lin & 7) * 8;
        *(uint4*)&smh[row * FSTR + cc] =
            *(const uint4*)(Qp + (size_t)(qt * 64 + row) * HD + cc);
    }
    __syncthreads();
    uint32_t aq[4][4];
#pragma unroll
    for (int ks = 0; ks < 4; ++ks) {
        const __half* p = smh + (wm + g) * FSTR + ks * 16 + 2 * t;
        aq[ks][0] = *(const uint32_t*)p;
        aq[ks][1] = *(const uint32_t*)(p + 8 * FSTR);
        aq[ks][2] = *(const uint32_t*)(p + 8);
        aq[ks][3] = *(const uint32_t*)(p + 8 * FSTR + 8);
    }
    __syncthreads();

    float m0 = -1e30f, m1 = -1e30f, l0 = 0.f, l1 = 0.f;
    float o[8][4];
#pragma unroll
    for (int n = 0; n < 8; ++n)
#pragma unroll
        for (int e = 0; e < 4; ++e) o[n][e] = 0.f;

    kv_issue(sbase, 0, Kp, Vtp, 0, tid);
    if (qt > 0) kv_issue(sbase, 1, Kp, Vtp, 1, tid);

    for (int kt = 0; kt <= qt; ++kt) {
        const int cur = kt & 1;
        if (kt < qt) cpa_wait1(); else cpa_wait0();
        __syncthreads();
        const uint32_t K0u = sbase + (uint32_t)cur * KBYTES + ldoff;
        const uint32_t Vtu = sbase + 2 * KBYTES + (uint32_t)cur * VBYTES + ldoff;

        float cs[8][4];
#pragma unroll
        for (int n = 0; n < 8; ++n)
#pragma unroll
            for (int e = 0; e < 4; ++e) cs[n][e] = 0.f;
#pragma unroll
        for (int ks = 0; ks < 4; ++ks) {
#pragma unroll
            for (int j = 0; j < 4; ++j) {
                uint32_t bf[4];
                ldm4(bf, K0u + (uint32_t)((16 * j) * FSTR + 16 * ks) * 2);
                mma_f16(cs[2 * j],     aq[ks][0], aq[ks][1], aq[ks][2], aq[ks][3],
                        bf[0], bf[1]);
                mma_f16(cs[2 * j + 1], aq[ks][0], aq[ks][1], aq[ks][2], aq[ks][3],
                        bf[2], bf[3]);
            }
        }

        if (kt == qt) {
            const int rowg = wm + g;
#pragma unroll
            for (int n = 0; n < 8; ++n) {
                int col = n * 8 + 2 * t;
                if (col     > rowg)     cs[n][0] = -1e30f;
                if (col + 1 > rowg)     cs[n][1] = -1e30f;
                if (col     > rowg + 8) cs[n][2] = -1e30f;
                if (col + 1 > rowg + 8) cs[n][3] = -1e30f;
            }
        }

        float mx0 = -1e30f, mx1 = -1e30f;
#pragma unroll
        for (int n = 0; n < 8; ++n) {
            mx0 = fmaxf(mx0, fmaxf(cs[n][0], cs[n][1]));
            mx1 = fmaxf(mx1, fmaxf(cs[n][2], cs[n][3]));
        }
        mx0 = fmaxf(mx0, __shfl_xor_sync(0xffffffffu, mx0, 1));
        mx0 = fmaxf(mx0, __shfl_xor_sync(0xffffffffu, mx0, 2));
        mx1 = fmaxf(mx1, __shfl_xor_sync(0xffffffffu, mx1, 1));
        mx1 = fmaxf(mx1, __shfl_xor_sync(0xffffffffu, mx1, 2));
        float mn0 = fmaxf(m0, mx0), mn1 = fmaxf(m1, mx1);
        float a0 = ex2(m0 - mn0), a1 = ex2(m1 - mn1);

        float s0 = 0.f, s1 = 0.f;
        uint32_t pa0[8], pa1[8];
#pragma unroll
        for (int n = 0; n < 8; ++n) {
            float p00 = ex2(cs[n][0] - mn0);
            float p01 = ex2(cs[n][1] - mn0);
            float p10 = ex2(cs[n][2] - mn1);
            float p11 = ex2(cs[n][3] - mn1);
            s0 += p00 + p01;
            s1 += p10 + p11;
            pa0[n] = pf16x2(p00, p01);
            pa1[n] = pf16x2(p10, p11);
        }
        s0 += __shfl_xor_sync(0xffffffffu, s0, 1);
        s0 += __shfl_xor_sync(0xffffffffu, s0, 2);
        s1 += __shfl_xor_sync(0xffffffffu, s1, 1);
        s1 += __shfl_xor_sync(0xffffffffu, s1, 2);
        l0 = l0 * a0 + s0;
        l1 = l1 * a1 + s1;
        m0 = mn0; m1 = mn1;
#pragma unroll
        for (int n = 0; n < 8; ++n) {
            o[n][0] *= a0; o[n][1] *= a0;
            o[n][2] *= a1; o[n][3] *= a1;
        }

#pragma unroll
        for (int ks = 0; ks < 4; ++ks) {
            uint32_t a0r = pa0[2 * ks],     a1r = pa1[2 * ks];
            uint32_t a2r = pa0[2 * ks + 1], a3r = pa1[2 * ks + 1];
#pragma unroll
            for (int j = 0; j < 4; ++j) {
                uint32_t vf[4];
                ldm4(vf, Vtu + (uint32_t)((16 * j) * FSTR + 16 * ks) * 2);
                mma_f16(o[2 * j],     a0r, a1r, a2r, a3r, vf[0], vf[1]);
                mma_f16(o[2 * j + 1], a0r, a1r, a2r, a3r, vf[2], vf[3]);
            }
        }
        __syncthreads();
        if (kt + 2 <= qt) kv_issue(sbase, cur, Kp, Vtp, kt + 2, tid);
    }

    float i0 = 1.f / l0, i1 = 1.f / l1;
    __half* d0 = attnout + ((size_t)(b * SEQL) + qt * 64 + wm + g) * D_MODEL + h * HD;
#pragma unroll
    for (int n = 0; n < 8; ++n) {
        int col = n * 8 + 2 * t;
        *(uint32_t*)(d0 + col) = pf16x2(o[n][0] * i0, o[n][1] * i0);
        *(uint32_t*)(d0 + 8 * D_MODEL + col) = pf16x2(o[n][2] * i1, o[n][3] * i1);
    }
}

// ---------------------------------------------------------------------------
extern "C" void kernel_launch(void* const* d_in, const int* in_sizes, int n_in,
                              void* d_out, int out_size)
{
    const float* x  = (const float*)d_in[0];
    const int*   tp = (const int*)d_in[1];
    const float* Wq = (const float*)d_in[2];
    const float* Wk = (const float*)d_in[3];
    const float* Wv = (const float*)d_in[4];
    const float* Wo = (const float*)d_in[5];
    float* out = (float*)d_out;

    __half *x16p, *w16p, *q16p, *k16p, *vtp, *a16p;
    cudaGetSymbolAddress((void**)&x16p, g_x16);
    cudaGetSymbolAddress((void**)&w16p, g_w16);
    cudaGetSymbolAddress((void**)&q16p, g_q16);
    cudaGetSymbolAddress((void**)&k16p, g_k16);
    cudaGetSymbolAddress((void**)&vtp, g_vt);
    cudaGetSymbolAddress((void**)&a16p, g_attn16);

    static int inited = 0;
    if (!inited) {
        cudaFuncSetAttribute(gemm_f16, cudaFuncAttributeMaxDynamicSharedMemorySize,
                             GEMM_SMEM);
        cudaFuncSetAttribute(flash_mma, cudaFuncAttributeMaxDynamicSharedMemorySize,
                             FLASH_SMEM);
        inited = 1;
    }

    const __half* w0 = w16p;
    const __half* w1 = w16p + (size_t)D_MODEL * D_MODEL;
    const __half* w2 = w16p + 2 * (size_t)D_MODEL * D_MODEL;
    const __half* w3 = w16p + 3 * (size_t)D_MODEL * D_MODEL;

    // converts + RoPE table in one launch
    cvt_all<<<(NCVT + SEQL * 32) / 256, 256>>>(
        (const float4*)x, (const float4*)Wq, (const float4*)Wk,
        (const float4*)Wv, (const float4*)Wo, tp);

    // fused QKV projection (+RoPE table, Q scale; fp16 outputs; V transposed)
    gemm_f16<<<dim3(D_MODEL / 128, MTOT / 128, 3), 128, GEMM_SMEM>>>(
        x16p, w0, w1, w2, out, q16p, k16p, vtp, 1, 3, 2);

    flash_mma<<<dim3(SEQL / 64, BSZ * NH), 128, FLASH_SMEM>>>(a16p);

    // output projection (fp32 result)
    gemm_f16<<<dim3(D_MODEL / 128, MTOT / 128, 1), 128, GEMM_SMEM>>>(
        a16p, w3, w3, w3, out, q16p, k16p, vtp, 0, 0, 0);
}